// round 7
// baseline (speedup 1.0000x reference)
#include <cuda_runtime.h>
#include <cuda_bf16.h>
#include <math.h>
#include <cstdint>

// CSELoss: loss = -mean_i [ s(i,i^1) - log(sum_{j!=i} exp(s_ij)) ], s = Xn Xn^T / alpha.
// Upper-triangle tiles only; each exp feeds both its row-sum and col-sum.
// 3 launches: normalize(+zero), expsum_mma, finalize(single-CTA reduce).

#define NROWS 8192
#define DD    128
#define TILE  128
#define AINV  20.0f
#define NT    (NROWS / TILE)          // 64
#define NTILES (NT * (NT + 1) / 2)    // 2080
#define STRB  272                     // smem row stride bytes: conflict-free ldmatrix

__device__ __nv_bfloat16  g_xb[NROWS * DD];    // bf16 normalized rows (MMA operands)
__device__ float          g_rowsum[NROWS];
__device__ float          g_tdot[NROWS / 2];   // normalized dot(x_{2p}, x_{2p+1})

// ---------------------------------------------------------------------------
__device__ __forceinline__ uint32_t smem_u32(const void* p) {
    uint32_t a;
    asm("{ .reg .u64 t; cvta.to.shared.u64 t, %1; cvt.u32.u64 %0, t; }" : "=r"(a) : "l"(p));
    return a;
}
__device__ __forceinline__ void ldm_x4(uint32_t& r0, uint32_t& r1, uint32_t& r2,
                                       uint32_t& r3, uint32_t addr) {
    asm volatile("ldmatrix.sync.aligned.m8n8.x4.shared.b16 {%0,%1,%2,%3}, [%4];"
                 : "=r"(r0), "=r"(r1), "=r"(r2), "=r"(r3) : "r"(addr));
}
__device__ __forceinline__ void mma16816(float* c, const uint32_t* a,
                                         uint32_t b0, uint32_t b1) {
    asm volatile("mma.sync.aligned.m16n8k16.row.col.f32.bf16.bf16.f32 "
                 "{%0,%1,%2,%3}, {%4,%5,%6,%7}, {%8,%9}, {%0,%1,%2,%3};"
                 : "+f"(c[0]), "+f"(c[1]), "+f"(c[2]), "+f"(c[3])
                 : "r"(a[0]), "r"(a[1]), "r"(a[2]), "r"(a[3]), "r"(b0), "r"(b1));
}

// ---------------------------------------------------------------------------
// One warp per PAIR of rows: norms, bf16 writes, pair dot. Also zeros g_rowsum.
__global__ void normalize_kernel(const float* __restrict__ in) {
    int gtid = blockIdx.x * blockDim.x + threadIdx.x;
    if (gtid < NROWS) g_rowsum[gtid] = 0.0f;
    int p    = gtid >> 5;              // pair index
    int lane = threadIdx.x & 31;
    if (p >= NROWS / 2) return;
    int r0 = p * 2;
    float4 v0 = ((const float4*)(in + (size_t)r0 * DD))[lane];
    float4 v1 = ((const float4*)(in + (size_t)(r0 + 1) * DD))[lane];
    float ss0 = v0.x*v0.x + v0.y*v0.y + v0.z*v0.z + v0.w*v0.w;
    float ss1 = v1.x*v1.x + v1.y*v1.y + v1.z*v1.z + v1.w*v1.w;
    float d   = v0.x*v1.x + v0.y*v1.y + v0.z*v1.z + v0.w*v1.w;
#pragma unroll
    for (int o = 16; o; o >>= 1) {
        ss0 += __shfl_xor_sync(0xffffffffu, ss0, o);
        ss1 += __shfl_xor_sync(0xffffffffu, ss1, o);
        d   += __shfl_xor_sync(0xffffffffu, d,   o);
    }
    float i0 = 1.0f / fmaxf(sqrtf(ss0), 1e-8f);
    float i1 = 1.0f / fmaxf(sqrtf(ss1), 1e-8f);
    v0.x *= i0; v0.y *= i0; v0.z *= i0; v0.w *= i0;
    v1.x *= i1; v1.y *= i1; v1.z *= i1; v1.w *= i1;
    __nv_bfloat162* b0 = (__nv_bfloat162*)(g_xb + (size_t)r0 * DD);
    __nv_bfloat162* b1 = (__nv_bfloat162*)(g_xb + (size_t)(r0 + 1) * DD);
    b0[lane*2+0] = __nv_bfloat162(__float2bfloat16_rn(v0.x), __float2bfloat16_rn(v0.y));
    b0[lane*2+1] = __nv_bfloat162(__float2bfloat16_rn(v0.z), __float2bfloat16_rn(v0.w));
    b1[lane*2+0] = __nv_bfloat162(__float2bfloat16_rn(v1.x), __float2bfloat16_rn(v1.y));
    b1[lane*2+1] = __nv_bfloat162(__float2bfloat16_rn(v1.z), __float2bfloat16_rn(v1.w));
    if (lane == 0) g_tdot[p] = d * i0 * i1;
}

// ---------------------------------------------------------------------------
// One CTA per upper-triangle tile (bi <= bj). 8 warps: 4(m) x 2(n), warp tile 32x64.
__global__ __launch_bounds__(256, 2)
void expsum_mma_kernel() {
    extern __shared__ __align__(16) char sm[];
    char* pA = sm;
    char* pB = sm + 128 * STRB;
    __shared__ float rsum[TILE];
    __shared__ float csum[TILE];

    int tid  = threadIdx.x;
    int lane = tid & 31;
    int wid  = tid >> 5;
    int warp_m = wid & 3;
    int warp_n = wid >> 2;

    // Linear tile index -> upper-triangle (bi, bj).
    int t = blockIdx.x, bi = 0;
    while (t >= NT - bi) { t -= NT - bi; bi++; }
    int bj = bi + t;
    bool diag = (bi == bj);
    int rowBase = bi * TILE;
    int colBase = bj * TILE;

#pragma unroll
    for (int it = 0; it < 8; it++) {
        int chunk = tid + it * 256;
        int r = chunk >> 4;
        int c = (chunk & 15) << 3;
        *(uint4*)(pA + r * STRB + c * 2) =
            *(const uint4*)&g_xb[(size_t)(rowBase + r) * DD + c];
        *(uint4*)(pB + r * STRB + c * 2) =
            *(const uint4*)&g_xb[(size_t)(colBase + r) * DD + c];
    }
    if (tid < TILE) { rsum[tid] = 0.0f; csum[tid] = 0.0f; }
    __syncthreads();

    uint32_t lrow = lane & 15;
    uint32_t lcol = (lane >> 4) << 4;
    uint32_t aAddr = smem_u32(pA) + (warp_m * 32 + lrow) * STRB + lcol;
    uint32_t bAddr = smem_u32(pB) + (warp_n * 64 + lrow) * STRB + lcol;

    float acc[2][8][4];
#pragma unroll
    for (int mf = 0; mf < 2; mf++)
#pragma unroll
        for (int nf = 0; nf < 8; nf++)
#pragma unroll
            for (int e = 0; e < 4; e++) acc[mf][nf][e] = 0.0f;

#pragma unroll
    for (int kk = 0; kk < 8; kk++) {
        uint32_t ka = kk * 32;
        uint32_t a[2][4];
        ldm_x4(a[0][0], a[0][1], a[0][2], a[0][3], aAddr + ka);
        ldm_x4(a[1][0], a[1][1], a[1][2], a[1][3], aAddr + 16 * STRB + ka);
        uint32_t br[4][4];
#pragma unroll
        for (int nb = 0; nb < 4; nb++)
            ldm_x4(br[nb][0], br[nb][1], br[nb][2], br[nb][3],
                   bAddr + nb * 16 * STRB + ka);
#pragma unroll
        for (int mf = 0; mf < 2; mf++)
#pragma unroll
            for (int nf = 0; nf < 8; nf++) {
                int nb = nf >> 1, odd = nf & 1;
                mma16816(acc[mf][nf], a[mf], br[nb][odd], br[nb][odd + 2]);
            }
    }

    // Epilogue. c-frag: lane (q=lane>>2, rm=lane&3) holds rows q,q+8 x cols 2rm,2rm+1.
    int q = lane >> 2, rm = lane & 3;
    float csA[8], csB[8];
#pragma unroll
    for (int nf = 0; nf < 8; nf++) { csA[nf] = 0.0f; csB[nf] = 0.0f; }

#pragma unroll
    for (int mf = 0; mf < 2; mf++) {
        int r0  = warp_m * 32 + mf * 16 + q;
        int gr0 = rowBase + r0, gr1 = gr0 + 8;
        float s0 = 0.0f, s1 = 0.0f;
#pragma unroll
        for (int nf = 0; nf < 8; nf++) {
            int gc = colBase + warp_n * 64 + nf * 8 + rm * 2;
            float e0 = __expf(acc[mf][nf][0] * AINV);
            float e1 = __expf(acc[mf][nf][1] * AINV);
            float e2 = __expf(acc[mf][nf][2] * AINV);
            float e3 = __expf(acc[mf][nf][3] * AINV);
            if (diag) {
                if (gr0 == gc)     e0 = 0.0f;
                if (gr0 == gc + 1) e1 = 0.0f;
                if (gr1 == gc)     e2 = 0.0f;
                if (gr1 == gc + 1) e3 = 0.0f;
            }
            s0 += e0 + e1;
            s1 += e2 + e3;
            csA[nf] += e0 + e2;
            csB[nf] += e1 + e3;
        }
        s0 += __shfl_xor_sync(0xffffffffu, s0, 1);
        s0 += __shfl_xor_sync(0xffffffffu, s0, 2);
        s1 += __shfl_xor_sync(0xffffffffu, s1, 1);
        s1 += __shfl_xor_sync(0xffffffffu, s1, 2);
        if (rm == 0) {
            atomicAdd(&rsum[r0], s0);
            atomicAdd(&rsum[r0 + 8], s1);
        }
    }

    if (!diag) {
#pragma unroll
        for (int nf = 0; nf < 8; nf++) {
#pragma unroll
            for (int o = 4; o <= 16; o <<= 1) {
                csA[nf] += __shfl_xor_sync(0xffffffffu, csA[nf], o);
                csB[nf] += __shfl_xor_sync(0xffffffffu, csB[nf], o);
            }
        }
        if (q == 0) {
#pragma unroll
            for (int nf = 0; nf < 8; nf++) {
                int c = warp_n * 64 + nf * 8 + rm * 2;
                atomicAdd(&csum[c],     csA[nf]);
                atomicAdd(&csum[c + 1], csB[nf]);
            }
        }
    }
    __syncthreads();

    if (tid < TILE) {
        atomicAdd(&g_rowsum[rowBase + tid], rsum[tid]);
        if (!diag) atomicAdd(&g_rowsum[colBase + tid], csum[tid]);
    }
}

// ---------------------------------------------------------------------------
// Single CTA, 1024 threads: deterministic tree reduction, direct write.
__global__ void finalize_kernel(float* out) {
    __shared__ float red[32];
    int tid = threadIdx.x;
    float l = 0.0f;
    for (int i = tid; i < NROWS; i += 1024)
        l += AINV * g_tdot[i >> 1] - logf(g_rowsum[i]);
#pragma unroll
    for (int o = 16; o; o >>= 1) l += __shfl_xor_sync(0xffffffffu, l, o);
    if ((tid & 31) == 0) red[tid >> 5] = l;
    __syncthreads();
    if (tid < 32) {
        float v = red[tid];
#pragma unroll
        for (int o = 16; o; o >>= 1) v += __shfl_xor_sync(0xffffffffu, v, o);
        if (tid == 0) out[0] = -v * (1.0f / NROWS);
    }
}

// ---------------------------------------------------------------------------
extern "C" void kernel_launch(void* const* d_in, const int* in_sizes, int n_in,
                              void* d_out, int out_size) {
    const float* in = (const float*)d_in[0];
    float* out = (float*)d_out;
    (void)in_sizes; (void)n_in; (void)out_size;

    int dynBytes = 2 * 128 * STRB;   // 69632
    (void)cudaFuncSetAttribute(expsum_mma_kernel,
                               cudaFuncAttributeMaxDynamicSharedMemorySize,
                               dynBytes);

    normalize_kernel<<<NROWS / 2 / 8, 256>>>(in);   // 512 CTAs x 256
    expsum_mma_kernel<<<NTILES, 256, dynBytes>>>();
    finalize_kernel<<<1, 1024>>>(out);
}

// round 9
// speedup vs baseline: 1.0697x; 1.0697x over previous
#include <cuda_runtime.h>
#include <cuda_bf16.h>
#include <math.h>
#include <cstdint>

// CSELoss: loss = -mean_i [ s(i,i^1) - log(sum_{j!=i} exp(s_ij)) ], s = Xn Xn^T / alpha.
// Upper-triangle only. CTA = row-band chunk of up to 4 tiles: A resident,
// B double-buffered with cp.async, rowsums accumulate in registers.

#define NROWS 8192
#define DD    128
#define TILE  128
#define AINV  20.0f
#define NT    (NROWS / TILE)          // 64
#define CHUNK 4
#define NCTAS 544                     // sum_{n=1..64} ceil(n/4)
#define STRB  272                     // smem row stride bytes
#define ABYTES (128 * STRB)           // 34816

__device__ __nv_bfloat16  g_xb[NROWS * DD];
__device__ float          g_rowsum[NROWS];
__device__ float          g_tdot[NROWS / 2];

// ---------------------------------------------------------------------------
__device__ __forceinline__ uint32_t smem_u32(const void* p) {
    uint32_t a;
    asm("{ .reg .u64 t; cvta.to.shared.u64 t, %1; cvt.u32.u64 %0, t; }" : "=r"(a) : "l"(p));
    return a;
}
__device__ __forceinline__ void cp16(uint32_t dst, const void* src) {
    asm volatile("cp.async.cg.shared.global [%0], [%1], 16;" :: "r"(dst), "l"(src));
}
__device__ __forceinline__ void ldm_x4(uint32_t& r0, uint32_t& r1, uint32_t& r2,
                                       uint32_t& r3, uint32_t addr) {
    asm volatile("ldmatrix.sync.aligned.m8n8.x4.shared.b16 {%0,%1,%2,%3}, [%4];"
                 : "=r"(r0), "=r"(r1), "=r"(r2), "=r"(r3) : "r"(addr));
}
__device__ __forceinline__ void mma16816(float* c, const uint32_t* a,
                                         uint32_t b0, uint32_t b1) {
    asm volatile("mma.sync.aligned.m16n8k16.row.col.f32.bf16.bf16.f32 "
                 "{%0,%1,%2,%3}, {%4,%5,%6,%7}, {%8,%9}, {%0,%1,%2,%3};"
                 : "+f"(c[0]), "+f"(c[1]), "+f"(c[2]), "+f"(c[3])
                 : "r"(a[0]), "r"(a[1]), "r"(a[2]), "r"(a[3]), "r"(b0), "r"(b1));
}

// ---------------------------------------------------------------------------
// One warp per PAIR of rows; also zeros g_rowsum.
__global__ void normalize_kernel(const float* __restrict__ in) {
    int gtid = blockIdx.x * blockDim.x + threadIdx.x;
    if (gtid < NROWS) g_rowsum[gtid] = 0.0f;
    int p    = gtid >> 5;
    int lane = threadIdx.x & 31;
    if (p >= NROWS / 2) return;
    int r0 = p * 2;
    float4 v0 = ((const float4*)(in + (size_t)r0 * DD))[lane];
    float4 v1 = ((const float4*)(in + (size_t)(r0 + 1) * DD))[lane];
    float ss0 = v0.x*v0.x + v0.y*v0.y + v0.z*v0.z + v0.w*v0.w;
    float ss1 = v1.x*v1.x + v1.y*v1.y + v1.z*v1.z + v1.w*v1.w;
    float d   = v0.x*v1.x + v0.y*v1.y + v0.z*v1.z + v0.w*v1.w;
#pragma unroll
    for (int o = 16; o; o >>= 1) {
        ss0 += __shfl_xor_sync(0xffffffffu, ss0, o);
        ss1 += __shfl_xor_sync(0xffffffffu, ss1, o);
        d   += __shfl_xor_sync(0xffffffffu, d,   o);
    }
    float i0 = 1.0f / fmaxf(sqrtf(ss0), 1e-8f);
    float i1 = 1.0f / fmaxf(sqrtf(ss1), 1e-8f);
    v0.x *= i0; v0.y *= i0; v0.z *= i0; v0.w *= i0;
    v1.x *= i1; v1.y *= i1; v1.z *= i1; v1.w *= i1;
    __nv_bfloat162* b0 = (__nv_bfloat162*)(g_xb + (size_t)r0 * DD);
    __nv_bfloat162* b1 = (__nv_bfloat162*)(g_xb + (size_t)(r0 + 1) * DD);
    b0[lane*2+0] = __nv_bfloat162(__float2bfloat16_rn(v0.x), __float2bfloat16_rn(v0.y));
    b0[lane*2+1] = __nv_bfloat162(__float2bfloat16_rn(v0.z), __float2bfloat16_rn(v0.w));
    b1[lane*2+0] = __nv_bfloat162(__float2bfloat16_rn(v1.x), __float2bfloat16_rn(v1.y));
    b1[lane*2+1] = __nv_bfloat162(__float2bfloat16_rn(v1.z), __float2bfloat16_rn(v1.w));
    if (lane == 0) g_tdot[p] = d * i0 * i1;
}

// ---------------------------------------------------------------------------
__global__ __launch_bounds__(256, 2)
void expsum_mma_kernel() {
    extern __shared__ __align__(16) char sm[];
    uint32_t sA  = smem_u32(sm);
    uint32_t sB0 = sA + ABYTES;
    uint32_t sB1 = sB0 + ABYTES;
    __shared__ float rsum[TILE];
    __shared__ float csum[TILE];

    int tid  = threadIdx.x;
    int lane = tid & 31;
    int wid  = tid >> 5;
    int warp_m = wid & 3;
    int warp_n = wid >> 2;

    // blockIdx -> (band bi, chunk start bjStart, ntile)
    int t = blockIdx.x, bi = 0;
    int cpb = (NT + CHUNK - 1) / CHUNK;
    while (t >= cpb) { t -= cpb; bi++; cpb = (NT - bi + CHUNK - 1) / CHUNK; }
    int bjStart = bi + t * CHUNK;
    int ntile   = min(CHUNK, NT - bjStart);
    int rowBase = bi * TILE;

    // Async-load A and B0.
    int r8 = tid >> 4;                  // row 0..127 (chunk base)
    int c8 = (tid & 15) << 3;           // bf16 col
#pragma unroll
    for (int it = 0; it < 8; it++) {
        int r = r8 + it * 16;
        uint32_t so = (uint32_t)r * STRB + (uint32_t)c8 * 2;
        cp16(sA + so,  &g_xb[(size_t)(rowBase + r) * DD + c8]);
        cp16(sB0 + so, &g_xb[(size_t)(bjStart * TILE + r) * DD + c8]);
    }
    asm volatile("cp.async.commit_group;");
    if (tid < TILE) { rsum[tid] = 0.0f; csum[tid] = 0.0f; }
    asm volatile("cp.async.wait_group 0;" ::: "memory");
    __syncthreads();

    uint32_t lrow = lane & 15;
    uint32_t lcol = (lane >> 4) << 4;
    uint32_t aAddr  = sA + (warp_m * 32 + lrow) * STRB + lcol;
    uint32_t bLocal = (warp_n * 64 + lrow) * STRB + lcol;

    int q = lane >> 2, rm = lane & 3;
    float rs[2][2] = {{0.f, 0.f}, {0.f, 0.f}};   // [mf][row q / q+8]

    for (int tt = 0; tt < ntile; tt++) {
        int bj = bjStart + tt;
        bool diag = (bj == bi);
        int colBase = bj * TILE;
        uint32_t bCur = (tt & 1) ? sB1 : sB0;
        uint32_t bNxt = (tt & 1) ? sB0 : sB1;

        // Prefetch next B tile (overlaps MMA + epilogue below).
        if (tt + 1 < ntile) {
#pragma unroll
            for (int it = 0; it < 8; it++) {
                int r = r8 + it * 16;
                cp16(bNxt + (uint32_t)r * STRB + (uint32_t)c8 * 2,
                     &g_xb[(size_t)((bj + 1) * TILE + r) * DD + c8]);
            }
            asm volatile("cp.async.commit_group;");
        }

        float acc[2][8][4];
#pragma unroll
        for (int mf = 0; mf < 2; mf++)
#pragma unroll
            for (int nf = 0; nf < 8; nf++)
#pragma unroll
                for (int e = 0; e < 4; e++) acc[mf][nf][e] = 0.0f;

        uint32_t bAddr = bCur + bLocal;
#pragma unroll
        for (int kk = 0; kk < 8; kk++) {
            uint32_t ka = kk * 32;
            uint32_t a[2][4];
            ldm_x4(a[0][0], a[0][1], a[0][2], a[0][3], aAddr + ka);
            ldm_x4(a[1][0], a[1][1], a[1][2], a[1][3], aAddr + 16 * STRB + ka);
            uint32_t br[4][4];
#pragma unroll
            for (int nb = 0; nb < 4; nb++)
                ldm_x4(br[nb][0], br[nb][1], br[nb][2], br[nb][3],
                       bAddr + nb * 16 * STRB + ka);
#pragma unroll
            for (int mf = 0; mf < 2; mf++)
#pragma unroll
                for (int nf = 0; nf < 8; nf++) {
                    int nb = nf >> 1, odd = nf & 1;
                    mma16816(acc[mf][nf], a[mf], br[nb][odd], br[nb][odd + 2]);
                }
        }

        // Epilogue: exp; accumulate row sums in regs, col sums per tile.
        float csA[8], csB[8];
#pragma unroll
        for (int nf = 0; nf < 8; nf++) { csA[nf] = 0.0f; csB[nf] = 0.0f; }
#pragma unroll
        for (int mf = 0; mf < 2; mf++) {
            int gr0 = rowBase + warp_m * 32 + mf * 16 + q;
            int gr1 = gr0 + 8;
#pragma unroll
            for (int nf = 0; nf < 8; nf++) {
                int gc = colBase + warp_n * 64 + nf * 8 + rm * 2;
                float e0 = __expf(acc[mf][nf][0] * AINV);
                float e1 = __expf(acc[mf][nf][1] * AINV);
                float e2 = __expf(acc[mf][nf][2] * AINV);
                float e3 = __expf(acc[mf][nf][3] * AINV);
                if (diag) {
                    if (gr0 == gc)     e0 = 0.0f;
                    if (gr0 == gc + 1) e1 = 0.0f;
                    if (gr1 == gc)     e2 = 0.0f;
                    if (gr1 == gc + 1) e3 = 0.0f;
                }
                rs[mf][0] += e0 + e1;
                rs[mf][1] += e2 + e3;
                csA[nf] += e0 + e2;
                csB[nf] += e1 + e3;
            }
        }

        if (!diag) {
#pragma unroll
            for (int nf = 0; nf < 8; nf++) {
#pragma unroll
                for (int o = 4; o <= 16; o <<= 1) {
                    csA[nf] += __shfl_xor_sync(0xffffffffu, csA[nf], o);
                    csB[nf] += __shfl_xor_sync(0xffffffffu, csB[nf], o);
                }
            }
            if (q == 0) {
#pragma unroll
                for (int nf = 0; nf < 8; nf++) {
                    int c = warp_n * 64 + nf * 8 + rm * 2;
                    atomicAdd(&csum[c],     csA[nf]);
                    atomicAdd(&csum[c + 1], csB[nf]);
                }
            }
            __syncthreads();
            if (tid < TILE) {
                atomicAdd(&g_rowsum[colBase + tid], csum[tid]);
                csum[tid] = 0.0f;
            }
        }

        // Next B ready + everyone done with bNxt's previous contents.
        asm volatile("cp.async.wait_group 0;" ::: "memory");
        __syncthreads();
    }

    // Row-sum reduction (accumulated over all tiles of the chunk).
#pragma unroll
    for (int mf = 0; mf < 2; mf++) {
        float s0 = rs[mf][0], s1 = rs[mf][1];
        s0 += __shfl_xor_sync(0xffffffffu, s0, 1);
        s0 += __shfl_xor_sync(0xffffffffu, s0, 2);
        s1 += __shfl_xor_sync(0xffffffffu, s1, 1);
        s1 += __shfl_xor_sync(0xffffffffu, s1, 2);
        if (rm == 0) {
            int r0 = warp_m * 32 + mf * 16 + q;
            atomicAdd(&rsum[r0], s0);
            atomicAdd(&rsum[r0 + 8], s1);
        }
    }
    __syncthreads();
    if (tid < TILE) atomicAdd(&g_rowsum[rowBase + tid], rsum[tid]);
}

// ---------------------------------------------------------------------------
__global__ void finalize_kernel(float* out) {
    __shared__ float red[32];
    int tid = threadIdx.x;
    float l = 0.0f;
    for (int i = tid; i < NROWS; i += 1024)
        l += AINV * g_tdot[i >> 1] - logf(g_rowsum[i]);
#pragma unroll
    for (int o = 16; o; o >>= 1) l += __shfl_xor_sync(0xffffffffu, l, o);
    if ((tid & 31) == 0) red[tid >> 5] = l;
    __syncthreads();
    if (tid < 32) {
        float v = red[tid];
#pragma unroll
        for (int o = 16; o; o >>= 1) v += __shfl_xor_sync(0xffffffffu, v, o);
        if (tid == 0) out[0] = -v * (1.0f / NROWS);
    }
}

// ---------------------------------------------------------------------------
extern "C" void kernel_launch(void* const* d_in, const int* in_sizes, int n_in,
                              void* d_out, int out_size) {
    const float* in = (const float*)d_in[0];
    float* out = (float*)d_out;
    (void)in_sizes; (void)n_in; (void)out_size;

    int dynBytes = 3 * ABYTES;   // A + 2 B buffers = 104448
    (void)cudaFuncSetAttribute(expsum_mma_kernel,
                               cudaFuncAttributeMaxDynamicSharedMemorySize,
                               dynBytes);

    normalize_kernel<<<NROWS / 2 / 8, 256>>>(in);
    expsum_mma_kernel<<<NCTAS, 256, dynBytes>>>();
    finalize_kernel<<<1, 1024>>>(out);
}

// round 10
// speedup vs baseline: 1.1609x; 1.0852x over previous
#include <cuda_runtime.h>
#include <cuda_bf16.h>
#include <math.h>
#include <cstdint>

// CSELoss: loss = -mean_i [ s(i,i^1) - log(sum_{j!=i} exp(s_ij)) ], s = Xn Xn^T / alpha.
// Upper-triangle only; A-resident chunks, cp.async double-buffered B.
// Operands pre-scaled by sqrt(20*log2(e)) so epilogue = single ex2 per element.

#define NROWS 8192
#define DD    128
#define TILE  128
#define AINV  20.0f
#define SQSC  5.37158769f             // sqrt(20 * log2(e))
#define NT    (NROWS / TILE)          // 64
#define CHUNK 4
#define NCTAS 544                     // sum_{n=1..64} ceil(n/4)
#define STRB  272                     // smem row stride bytes
#define ABYTES (128 * STRB)           // 34816

__device__ __nv_bfloat16  g_xb[NROWS * DD];    // sqrt(20*log2e)-scaled normalized rows
__device__ float          g_rowsum[NROWS];
__device__ float          g_tdot[NROWS / 2];

// ---------------------------------------------------------------------------
__device__ __forceinline__ uint32_t smem_u32(const void* p) {
    uint32_t a;
    asm("{ .reg .u64 t; cvta.to.shared.u64 t, %1; cvt.u32.u64 %0, t; }" : "=r"(a) : "l"(p));
    return a;
}
__device__ __forceinline__ void cp16(uint32_t dst, const void* src) {
    asm volatile("cp.async.cg.shared.global [%0], [%1], 16;" :: "r"(dst), "l"(src));
}
__device__ __forceinline__ void ldm_x4(uint32_t& r0, uint32_t& r1, uint32_t& r2,
                                       uint32_t& r3, uint32_t addr) {
    asm volatile("ldmatrix.sync.aligned.m8n8.x4.shared.b16 {%0,%1,%2,%3}, [%4];"
                 : "=r"(r0), "=r"(r1), "=r"(r2), "=r"(r3) : "r"(addr));
}
__device__ __forceinline__ void mma16816(float* c, const uint32_t* a,
                                         uint32_t b0, uint32_t b1) {
    asm volatile("mma.sync.aligned.m16n8k16.row.col.f32.bf16.bf16.f32 "
                 "{%0,%1,%2,%3}, {%4,%5,%6,%7}, {%8,%9}, {%0,%1,%2,%3};"
                 : "+f"(c[0]), "+f"(c[1]), "+f"(c[2]), "+f"(c[3])
                 : "r"(a[0]), "r"(a[1]), "r"(a[2]), "r"(a[3]), "r"(b0), "r"(b1));
}
__device__ __forceinline__ float ex2(float x) {
    float y;
    asm("ex2.approx.ftz.f32 %0, %1;" : "=f"(y) : "f"(x));
    return y;
}

// ---------------------------------------------------------------------------
// One warp per PAIR of rows; also zeros g_rowsum. tdot stays fp32/unscaled.
__global__ void normalize_kernel(const float* __restrict__ in) {
    int gtid = blockIdx.x * blockDim.x + threadIdx.x;
    if (gtid < NROWS) g_rowsum[gtid] = 0.0f;
    int p    = gtid >> 5;
    int lane = threadIdx.x & 31;
    if (p >= NROWS / 2) return;
    int r0 = p * 2;
    float4 v0 = ((const float4*)(in + (size_t)r0 * DD))[lane];
    float4 v1 = ((const float4*)(in + (size_t)(r0 + 1) * DD))[lane];
    float ss0 = v0.x*v0.x + v0.y*v0.y + v0.z*v0.z + v0.w*v0.w;
    float ss1 = v1.x*v1.x + v1.y*v1.y + v1.z*v1.z + v1.w*v1.w;
    float d   = v0.x*v1.x + v0.y*v1.y + v0.z*v1.z + v0.w*v1.w;
#pragma unroll
    for (int o = 16; o; o >>= 1) {
        ss0 += __shfl_xor_sync(0xffffffffu, ss0, o);
        ss1 += __shfl_xor_sync(0xffffffffu, ss1, o);
        d   += __shfl_xor_sync(0xffffffffu, d,   o);
    }
    float i0 = 1.0f / fmaxf(sqrtf(ss0), 1e-8f);
    float i1 = 1.0f / fmaxf(sqrtf(ss1), 1e-8f);
    if (lane == 0) g_tdot[p] = d * i0 * i1;
    float s0 = i0 * SQSC, s1 = i1 * SQSC;
    v0.x *= s0; v0.y *= s0; v0.z *= s0; v0.w *= s0;
    v1.x *= s1; v1.y *= s1; v1.z *= s1; v1.w *= s1;
    __nv_bfloat162* b0 = (__nv_bfloat162*)(g_xb + (size_t)r0 * DD);
    __nv_bfloat162* b1 = (__nv_bfloat162*)(g_xb + (size_t)(r0 + 1) * DD);
    b0[lane*2+0] = __nv_bfloat162(__float2bfloat16_rn(v0.x), __float2bfloat16_rn(v0.y));
    b0[lane*2+1] = __nv_bfloat162(__float2bfloat16_rn(v0.z), __float2bfloat16_rn(v0.w));
    b1[lane*2+0] = __nv_bfloat162(__float2bfloat16_rn(v1.x), __float2bfloat16_rn(v1.y));
    b1[lane*2+1] = __nv_bfloat162(__float2bfloat16_rn(v1.z), __float2bfloat16_rn(v1.w));
}

// ---------------------------------------------------------------------------
__global__ __launch_bounds__(256, 2)
void expsum_mma_kernel() {
    extern __shared__ __align__(16) char sm[];
    uint32_t sA  = smem_u32(sm);
    uint32_t sB0 = sA + ABYTES;
    uint32_t sB1 = sB0 + ABYTES;
    __shared__ float rsum[TILE];
    __shared__ float csum[TILE];

    int tid  = threadIdx.x;
    int lane = tid & 31;
    int wid  = tid >> 5;
    int warp_m = wid & 3;
    int warp_n = wid >> 2;

    // blockIdx -> (band bi, chunk start bjStart, ntile)
    int t = blockIdx.x, bi = 0;
    int cpb = (NT + CHUNK - 1) / CHUNK;
    while (t >= cpb) { t -= cpb; bi++; cpb = (NT - bi + CHUNK - 1) / CHUNK; }
    int bjStart = bi + t * CHUNK;
    int ntile   = min(CHUNK, NT - bjStart);
    int rowBase = bi * TILE;

    // Async-load A and B0.
    int r8 = tid >> 4;
    int c8 = (tid & 15) << 3;
#pragma unroll
    for (int it = 0; it < 8; it++) {
        int r = r8 + it * 16;
        uint32_t so = (uint32_t)r * STRB + (uint32_t)c8 * 2;
        cp16(sA + so,  &g_xb[(size_t)(rowBase + r) * DD + c8]);
        cp16(sB0 + so, &g_xb[(size_t)(bjStart * TILE + r) * DD + c8]);
    }
    asm volatile("cp.async.commit_group;");
    if (tid < TILE) { rsum[tid] = 0.0f; csum[tid] = 0.0f; }
    asm volatile("cp.async.wait_group 0;" ::: "memory");
    __syncthreads();

    uint32_t lrow = lane & 15;
    uint32_t lcol = (lane >> 4) << 4;
    uint32_t aAddr  = sA + (warp_m * 32 + lrow) * STRB + lcol;
    uint32_t bLocal = (warp_n * 64 + lrow) * STRB + lcol;

    int q = lane >> 2, rm = lane & 3;
    float rs[2][2] = {{0.f, 0.f}, {0.f, 0.f}};

    for (int tt = 0; tt < ntile; tt++) {
        int bj = bjStart + tt;
        bool diag = (bj == bi);
        int colBase = bj * TILE;
        uint32_t bCur = (tt & 1) ? sB1 : sB0;
        uint32_t bNxt = (tt & 1) ? sB0 : sB1;

        if (tt + 1 < ntile) {
#pragma unroll
            for (int it = 0; it < 8; it++) {
                int r = r8 + it * 16;
                cp16(bNxt + (uint32_t)r * STRB + (uint32_t)c8 * 2,
                     &g_xb[(size_t)((bj + 1) * TILE + r) * DD + c8]);
            }
            asm volatile("cp.async.commit_group;");
        }

        float acc[2][8][4];
#pragma unroll
        for (int mf = 0; mf < 2; mf++)
#pragma unroll
            for (int nf = 0; nf < 8; nf++)
#pragma unroll
                for (int e = 0; e < 4; e++) acc[mf][nf][e] = 0.0f;

        uint32_t bAddr = bCur + bLocal;
#pragma unroll
        for (int kk = 0; kk < 8; kk++) {
            uint32_t ka = kk * 32;
            uint32_t a[2][4];
            ldm_x4(a[0][0], a[0][1], a[0][2], a[0][3], aAddr + ka);
            ldm_x4(a[1][0], a[1][1], a[1][2], a[1][3], aAddr + 16 * STRB + ka);
            uint32_t br[4][4];
#pragma unroll
            for (int nb = 0; nb < 4; nb++)
                ldm_x4(br[nb][0], br[nb][1], br[nb][2], br[nb][3],
                       bAddr + nb * 16 * STRB + ka);
#pragma unroll
            for (int mf = 0; mf < 2; mf++)
#pragma unroll
                for (int nf = 0; nf < 8; nf++) {
                    int nb = nf >> 1, odd = nf & 1;
                    mma16816(acc[mf][nf], a[mf], br[nb][odd], br[nb][odd + 2]);
                }
        }

        // Epilogue: acc already = 20*log2e*cos -> single ex2 per element.
        float csA[8], csB[8];
#pragma unroll
        for (int nf = 0; nf < 8; nf++) { csA[nf] = 0.0f; csB[nf] = 0.0f; }
#pragma unroll
        for (int mf = 0; mf < 2; mf++) {
            int gr0 = rowBase + warp_m * 32 + mf * 16 + q;
            int gr1 = gr0 + 8;
#pragma unroll
            for (int nf = 0; nf < 8; nf++) {
                int gc = colBase + warp_n * 64 + nf * 8 + rm * 2;
                float e0 = ex2(acc[mf][nf][0]);
                float e1 = ex2(acc[mf][nf][1]);
                float e2 = ex2(acc[mf][nf][2]);
                float e3 = ex2(acc[mf][nf][3]);
                if (diag) {
                    if (gr0 == gc)     e0 = 0.0f;
                    if (gr0 == gc + 1) e1 = 0.0f;
                    if (gr1 == gc)     e2 = 0.0f;
                    if (gr1 == gc + 1) e3 = 0.0f;
                }
                rs[mf][0] += e0 + e1;
                rs[mf][1] += e2 + e3;
                csA[nf] += e0 + e2;
                csB[nf] += e1 + e3;
            }
        }

        if (!diag) {
#pragma unroll
            for (int nf = 0; nf < 8; nf++) {
#pragma unroll
                for (int o = 4; o <= 16; o <<= 1) {
                    csA[nf] += __shfl_xor_sync(0xffffffffu, csA[nf], o);
                    csB[nf] += __shfl_xor_sync(0xffffffffu, csB[nf], o);
                }
            }
            if (q == 0) {
#pragma unroll
                for (int nf = 0; nf < 8; nf++) {
                    int c = warp_n * 64 + nf * 8 + rm * 2;
                    atomicAdd(&csum[c],     csA[nf]);
                    atomicAdd(&csum[c + 1], csB[nf]);
                }
            }
            __syncthreads();
            if (tid < TILE) {
                atomicAdd(&g_rowsum[colBase + tid], csum[tid]);
                csum[tid] = 0.0f;
            }
        }

        asm volatile("cp.async.wait_group 0;" ::: "memory");
        __syncthreads();
    }

#pragma unroll
    for (int mf = 0; mf < 2; mf++) {
        float s0 = rs[mf][0], s1 = rs[mf][1];
        s0 += __shfl_xor_sync(0xffffffffu, s0, 1);
        s0 += __shfl_xor_sync(0xffffffffu, s0, 2);
        s1 += __shfl_xor_sync(0xffffffffu, s1, 1);
        s1 += __shfl_xor_sync(0xffffffffu, s1, 2);
        if (rm == 0) {
            int r0 = warp_m * 32 + mf * 16 + q;
            atomicAdd(&rsum[r0], s0);
            atomicAdd(&rsum[r0 + 8], s1);
        }
    }
    __syncthreads();
    if (tid < TILE) atomicAdd(&g_rowsum[rowBase + tid], rsum[tid]);
}

// ---------------------------------------------------------------------------
__global__ void finalize_kernel(float* out) {
    __shared__ float red[32];
    int tid = threadIdx.x;
    float l = 0.0f;
    for (int i = tid; i < NROWS; i += 1024)
        l += AINV * g_tdot[i >> 1] - logf(g_rowsum[i]);
#pragma unroll
    for (int o = 16; o; o >>= 1) l += __shfl_xor_sync(0xffffffffu, l, o);
    if ((tid & 31) == 0) red[tid >> 5] = l;
    __syncthreads();
    if (tid < 32) {
        float v = red[tid];
#pragma unroll
        for (int o = 16; o; o >>= 1) v += __shfl_xor_sync(0xffffffffu, v, o);
        if (tid == 0) out[0] = -v * (1.0f / NROWS);
    }
}

// ---------------------------------------------------------------------------
extern "C" void kernel_launch(void* const* d_in, const int* in_sizes, int n_in,
                              void* d_out, int out_size) {
    const float* in = (const float*)d_in[0];
    float* out = (float*)d_out;
    (void)in_sizes; (void)n_in; (void)out_size;

    int dynBytes = 3 * ABYTES;   // 104448
    (void)cudaFuncSetAttribute(expsum_mma_kernel,
                               cudaFuncAttributeMaxDynamicSharedMemorySize,
                               dynBytes);

    normalize_kernel<<<NROWS / 2 / 8, 256>>>(in);
    expsum_mma_kernel<<<NCTAS, 256, dynBytes>>>();
    finalize_kernel<<<1, 1024>>>(out);
}